// round 2
// baseline (speedup 1.0000x reference)
#include <cuda_runtime.h>

// Histogram matching: BINS=32, SIGMA=5, DELTA=1
// Shapes: dst, ref: (2,1,64,128,128) fp32; out same.
#define N_VOX   (64 * 128 * 128)   // 1048576 voxels per image
#define N_IMG   2
#define H_BLOCKS 74                // hist blocks per job: 74*4 = 296 = 2 per SM
#define LUT_N   4096               // lerp intervals; nodes = LUT_N+1
#define SLOTS   36                 // padded per-warp hist: slot = c + 2, c in [-2, 33]

// Scratch (device globals; fully rewritten every launch -> graph-replay safe)
__device__ float g_part[4 * H_BLOCKS * 32];     // per-block histogram partials
__device__ float g_lut[N_IMG * (LUT_N + 1)];    // matched-value LUT per image

// ---------------------------------------------------------------------------
// Kernel 1: soft histograms for 4 jobs (dst img0, dst img1, ref img0, ref img1)
// hist[c] = S(c) - S(c+1), S(c) = sigmoid(5*(x - c + 0.5)).
// Active boundaries per voxel (j = floor(x)): c = j-1 .. j+3.
//   z(c) = 5*(x - c + 0.5) = 5t + {7.5, 2.5, -2.5, -7.5, -12.5} for c=j-1..j+3
//   |z| >= 12.5  -> saturate (error <= 3.7e-6/voxel)
//   z in [-12.5,-7.5] (c=j+3) -> S ~= e^z  (error <= E^2 ~ 3e-7/voxel)
// One __expf + 4 RCP per voxel; 6 unconditional padded-slot RMWs.
// ---------------------------------------------------------------------------
__global__ void __launch_bounds__(256) hist_kernel(const float* __restrict__ dst,
                                                   const float* __restrict__ ref)
{
    __shared__ float hs[8 * SLOTS * 32];   // [warp][slot][lane]; bank==lane: conflict-free
    __shared__ float part2[8 * 32];

    const int tid  = threadIdx.x;
    const int lane = tid & 31;
    const int warp = tid >> 5;
    const int job  = blockIdx.y;        // 0,1 = dst; 2,3 = ref
    const float* src = (job < 2 ? dst : ref) + (size_t)(job & 1) * N_VOX;

    for (int i = tid; i < 8 * SLOTS * 32; i += 256) hs[i] = 0.0f;
    __syncthreads();

    float* hp = &hs[warp * SLOTS * 32 + lane];   // + slot*32

    const float4* src4 = (const float4*)src;
    const int nthreads = H_BLOCKS * 256;
    for (int i = blockIdx.x * 256 + tid; i < N_VOX / 4; i += nthreads) {
        float4 v = src4[i];
        float vals[4] = {v.x, v.y, v.z, v.w};
        #pragma unroll
        for (int e = 0; e < 4; e++) {
            float x = vals[e] * 31.0f;            // in [0, 31)
            int   j = (int)x;
            j = min(j, 30);
            float t5 = (x - (float)j) * 5.0f;     // [0, 5)
            float e5 = __expf(t5);
            // E_c = exp(z(c)); S = E / (1 + E)
            float E3 = e5 * 3.7266532e-6f;        // z = 5t - 12.5 ; S ~= E3
            float E2 = e5 * 5.5308438e-4f;        // z = 5t - 7.5
            float E1 = e5 * 8.2084998e-2f;        // z = 5t - 2.5
            float E0 = e5 * 12.182494f;           // z = 5t + 2.5
            float Em = e5 * 1808.0424f;           // z = 5t + 7.5
            float S2 = __fdividef(E2, 1.0f + E2);
            float S1 = __fdividef(E1, 1.0f + E1);
            float S0 = __fdividef(E0, 1.0f + E0);
            float Sm = __fdividef(Em, 1.0f + Em);
            float* p = hp + j * 32;               // slot(c) = c + 2
            p[5 * 32] += E3;                      // c = j+3
            p[4 * 32] += S2 - E3;                 // c = j+2
            p[3 * 32] += S1 - S2;                 // c = j+1
            p[2 * 32] += S0 - S1;                 // c = j
            p[1 * 32] += Sm - S0;                 // c = j-1
            p[0 * 32] += 1.0f - Sm;               // c = j-2   (S(j-2) ~= 1)
        }
    }
    __syncthreads();

    // Reduce lane-columns per bin (bin b lives in slot b+2). Skewed start: conflict-free.
    {
        int w = warp, bin = lane;                 // 256 threads = 8 warps x 32 bins
        float s = 0.0f;
        #pragma unroll
        for (int i = 0; i < 32; i++) {
            int l = (lane + i) & 31;
            s += hs[(w * SLOTS + bin + 2) * 32 + l];
        }
        part2[w * 32 + bin] = s;
    }
    __syncthreads();
    if (tid < 32) {
        float s = 0.0f;
        #pragma unroll
        for (int w = 0; w < 8; w++) s += part2[w * 32 + tid];
        g_part[(job * H_BLOCKS + blockIdx.x) * 32 + tid] = s;
    }
}

// ---------------------------------------------------------------------------
// Kernel 2: every block redundantly computes cdf + argmin tables (cheap),
// then blocks cooperatively build the matched-value LUT:
//   f(x) = (sum_k exp(-(x-k)^2/50) * table[k]) / (sum_k exp(...)) / 31
// ---------------------------------------------------------------------------
__global__ void __launch_bounds__(256) lut_kernel()
{
    __shared__ float cdf[4][32];
    __shared__ float tab[2][32];
    const int tid = threadIdx.x;

    if (tid < 128) {
        int job = tid >> 5, bin = tid & 31;
        float s = 0.0f;
        #pragma unroll 1
        for (int b = 0; b < H_BLOCKS; b++)
            s += g_part[(job * H_BLOCKS + b) * 32 + bin];
        cdf[job][bin] = s;                         // raw hist for now
    }
    __syncthreads();
    if (tid < 4) {                                 // normalize + cumsum (serial, tiny)
        float tot = 0.0f;
        for (int b = 0; b < 32; b++) tot += fabsf(cdf[tid][b]);
        tot = fmaxf(tot, 1e-12f);
        float run = 0.0f;
        for (int b = 0; b < 32; b++) { run += cdf[tid][b] / tot; cdf[tid][b] = run; }
    }
    __syncthreads();
    if (tid < 64) {                                // argmin tables (first-match ties)
        int bc = tid >> 5, i = tid & 31;
        float cd = cdf[bc][i];
        int best = 0;
        float bd = fabsf(cd - cdf[bc + 2][0]);
        for (int jj = 1; jj < 32; jj++) {
            float d = fabsf(cd - cdf[bc + 2][jj]);
            if (d < bd) { bd = d; best = jj; }
        }
        tab[bc][i] = (float)best;
    }
    __syncthreads();

    const int total = N_IMG * (LUT_N + 1);
    for (int e = blockIdx.x * blockDim.x + tid; e < total; e += gridDim.x * blockDim.x) {
        int im = e / (LUT_N + 1);
        int i  = e - im * (LUT_N + 1);
        float x = (float)i * (31.0f / (float)LUT_N);
        float num = 0.0f, den = 0.0f;
        #pragma unroll
        for (int k = 0; k < 32; k++) {
            float d = x - (float)k;
            float w = __expf(d * d * -0.02f);      // exp(-(x-k)^2/50)
            den += w;
            num += w * tab[im][k];
        }
        g_lut[e] = __fdividef(num, den) * (1.0f / 31.0f);
    }
}

// ---------------------------------------------------------------------------
// Kernel 3: per-voxel LUT lerp. lut coordinate u = v*LUT_N (v in [0,1)).
// ---------------------------------------------------------------------------
__global__ void __launch_bounds__(256) apply_kernel(const float* __restrict__ dst,
                                                    float* __restrict__ out)
{
    __shared__ float lut[LUT_N + 1];
    const int im  = blockIdx.y;
    const int tid = threadIdx.x;

    for (int i = tid; i < LUT_N + 1; i += 256)
        lut[i] = g_lut[im * (LUT_N + 1) + i];
    __syncthreads();

    const float4* in4  = (const float4*)(dst + (size_t)im * N_VOX);
    float4*       out4 = (float4*)(out + (size_t)im * N_VOX);
    const int nthreads = gridDim.x * 256;

    for (int i = blockIdx.x * 256 + tid; i < N_VOX / 4; i += nthreads) {
        float4 v = in4[i];
        float vals[4] = {v.x, v.y, v.z, v.w};
        float res[4];
        #pragma unroll
        for (int e = 0; e < 4; e++) {
            float u = vals[e] * (float)LUT_N;
            int idx = (int)u;
            idx = min(max(idx, 0), LUT_N - 1);
            float f = u - (float)idx;
            float a = lut[idx];
            float b = lut[idx + 1];
            res[e] = a + f * (b - a);
        }
        out4[i] = make_float4(res[0], res[1], res[2], res[3]);
    }
}

extern "C" void kernel_launch(void* const* d_in, const int* in_sizes, int n_in,
                              void* d_out, int out_size)
{
    const float* dst = (const float*)d_in[0];
    const float* ref = (const float*)d_in[1];
    float* out = (float*)d_out;

    hist_kernel<<<dim3(H_BLOCKS, 4), 256>>>(dst, ref);
    lut_kernel<<<32, 256>>>();
    apply_kernel<<<dim3(148, N_IMG), 256>>>(dst, out);
}

// round 5
// speedup vs baseline: 1.7036x; 1.7036x over previous
#include <cuda_runtime.h>

// Histogram matching: BINS=32, SIGMA=5, DELTA=1
// Shapes: dst, ref: (2,1,64,128,128) fp32; out same.
#define N_VOX    (64 * 128 * 128)    // 1048576 voxels per image
#define N_IMG    2
#define NBLK     296                 // 2 blocks per SM (148 SMs), co-resident
#define NTHREADS 512                 // 16 warps
#define H_SUB    74                  // hist sub-blocks per job (4 jobs * 74 = 296)
#define SLOTS    36                  // padded per-warp hist: slot = c + 2, c in [-2, 33]
#define LUT_N    1024                // lerp intervals; nodes = LUT_N + 1

// Scratch (device globals; fully rewritten or self-restoring every launch)
__device__ float g_part[4 * H_SUB * 32];   // per-block histogram partials
__device__ int           g_bar_cnt  = 0;   // returns to 0 every launch
__device__ volatile int  g_bar_sense = 0;  // flips once per launch (value-agnostic protocol)

// ---------------------------------------------------------------------------
// Single persistent kernel:
//  P1: soft histograms (4 jobs = {dst,ref} x {img0,img1}) -> g_part
//  [grid barrier]
//  P2: every block redundantly reduces g_part -> 32-bin hists, cdf, argmin
//      table, and builds a 1025-node matched-value LUT for its image in smem
//  P3: stream dst through the LUT (lerp) -> out
// ---------------------------------------------------------------------------
extern __shared__ float dyn_smem[];   // 16*36*32 floats = 73728 B (P1); reused as LUT (P2/P3)

__global__ void __launch_bounds__(NTHREADS, 2)
fused_kernel(const float* __restrict__ dst, const float* __restrict__ ref,
             float* __restrict__ out)
{
    __shared__ float part2[16 * 32];
    __shared__ float red[128 * 4];
    __shared__ float cdf[4][32];
    __shared__ float tab[2][32];
    __shared__ float Vk[32];

    const int tid  = threadIdx.x;
    const int lane = tid & 31;
    const int warp = tid >> 5;
    const int bid  = blockIdx.x;

    // ======================= P1: soft histogram =======================
    // hist[c] = S(c) - S(c+1), S(c) = sigmoid(5*(x - c + 0.5)).
    // Active boundaries c = j-1..j+3 (j=floor(x)); |z|>=12.5 saturates
    // (err <= 3.7e-6/voxel); z in [-12.5,-7.5] uses S ~= e^z.
    {
        const int job = bid & 3;            // 0,1 = dst; 2,3 = ref
        const int sub = bid >> 2;           // 0..73
        const float* src = (job < 2 ? dst : ref) + (size_t)(job & 1) * N_VOX;

        float* hs = dyn_smem;               // [warp][slot][lane]
        for (int i = tid; i < 16 * SLOTS * 32; i += NTHREADS) hs[i] = 0.0f;
        __syncthreads();

        float* hp = &hs[warp * SLOTS * 32 + lane];

        const float4* src4 = (const float4*)src;
        const int nthreads = H_SUB * NTHREADS;
        for (int i = sub * NTHREADS + tid; i < N_VOX / 4; i += nthreads) {
            float4 v = src4[i];
            float vals[4] = {v.x, v.y, v.z, v.w};
            #pragma unroll
            for (int e = 0; e < 4; e++) {
                float x = vals[e] * 31.0f;        // [0, 31)
                int   j = (int)x;
                j = min(j, 30);
                float t5 = (x - (float)j) * 5.0f; // [0, 5)
                float e5 = __expf(t5);
                float E3 = e5 * 3.7266532e-6f;    // z = 5t - 12.5 ; S ~= E3
                float E2 = e5 * 5.5308438e-4f;    // z = 5t - 7.5
                float E1 = e5 * 8.2084998e-2f;    // z = 5t - 2.5
                float E0 = e5 * 12.182494f;       // z = 5t + 2.5
                float Em = e5 * 1808.0424f;       // z = 5t + 7.5
                float S2 = __fdividef(E2, 1.0f + E2);
                float S1 = __fdividef(E1, 1.0f + E1);
                float S0 = __fdividef(E0, 1.0f + E0);
                float Sm = __fdividef(Em, 1.0f + Em);
                float* p = hp + j * 32;           // slot(c) = c + 2
                p[5 * 32] += E3;                  // c = j+3
                p[4 * 32] += S2 - E3;             // c = j+2
                p[3 * 32] += S1 - S2;             // c = j+1
                p[2 * 32] += S0 - S1;             // c = j
                p[1 * 32] += Sm - S0;             // c = j-1
                p[0 * 32] += 1.0f - Sm;           // c = j-2 (S(j-2) ~= 1)
            }
        }
        __syncthreads();

        // Reduce 16 warps x 32 lanes per bin; skewed lane start: conflict-free.
        {
            int w = warp, bin = lane;             // 512 threads = 16 warps x 32 bins
            float s = 0.0f;
            #pragma unroll
            for (int i = 0; i < 32; i++) {
                int l = (lane + i) & 31;
                s += hs[(w * SLOTS + bin + 2) * 32 + l];
            }
            part2[w * 32 + bin] = s;
        }
        __syncthreads();
        if (tid < 32) {
            float s = 0.0f;
            #pragma unroll
            for (int w = 0; w < 16; w++) s += part2[w * 32 + tid];
            g_part[(job * H_SUB + sub) * 32 + tid] = s;
        }
    }

    // ======================= grid barrier =======================
    __threadfence();          // publish g_part (all threads)
    __syncthreads();
    if (tid == 0) {
        int s = g_bar_sense;  // stable: flips only after ALL arrive
        int p = atomicAdd(&g_bar_cnt, 1);
        if (p == NBLK - 1) {
            g_bar_cnt = 0;    // self-reset for next launch
            __threadfence();
            g_bar_sense = s ^ 1;
        } else {
            while (g_bar_sense == s) __nanosleep(64);
        }
    }
    __syncthreads();
    __threadfence();          // acquire g_part

    // ======== P2: redundant per-block hist reduce + cdf + table + LUT ========
    {
        // 128 (job,bin) pairs, 4 partial-summers each
        int pair = tid >> 2;          // 0..127
        int q    = tid & 3;
        {
            int job = pair >> 5, bin = pair & 31;
            float s = 0.0f;
            for (int b = q; b < H_SUB; b += 4)
                s += g_part[(job * H_SUB + b) * 32 + bin];
            red[pair * 4 + q] = s;
        }
        if (tid < 32) Vk[tid] = __expf((float)(tid * tid) * -0.02f);  // exp(-k^2/50)
        __syncthreads();
        if (tid < 128) {
            int job = tid >> 5, bin = tid & 31;
            cdf[job][bin] = (red[tid * 4 + 0] + red[tid * 4 + 1])
                          + (red[tid * 4 + 2] + red[tid * 4 + 3]);
        }
        __syncthreads();
        if (tid < 4) {                 // normalize + cumsum (serial, tiny)
            float tot = 0.0f;
            for (int b = 0; b < 32; b++) tot += fabsf(cdf[tid][b]);
            tot = fmaxf(tot, 1e-12f);
            float run = 0.0f;
            for (int b = 0; b < 32; b++) { run += cdf[tid][b] / tot; cdf[tid][b] = run; }
        }
        __syncthreads();
        if (tid < 64) {                // argmin tables (first-match ties)
            int bc = tid >> 5, i = tid & 31;
            float cd = cdf[bc][i];
            int best = 0;
            float bd = fabsf(cd - cdf[bc + 2][0]);
            for (int jj = 1; jj < 32; jj++) {
                float d = fabsf(cd - cdf[bc + 2][jj]);
                if (d < bd) { bd = d; best = jj; }
            }
            tab[bc][i] = (float)best;
        }
        __syncthreads();

        // Build this block's image LUT in smem (reuse dyn_smem).
        // f(x) = softmax_k(-(x-k)^2/50) . tab / 31, with
        // exp(-(x-k)^2/50) = C * U^k * V_k, U = exp(x/25) (C cancels).
        const int im = bid & 1;
        float* lut = dyn_smem;
        for (int i = tid; i < LUT_N + 1; i += NTHREADS) {
            float x = (float)i * (31.0f / (float)LUT_N);
            float U = __expf(x * 0.04f);
            float p = 1.0f, num = 0.0f, den = 0.0f;
            #pragma unroll
            for (int k = 0; k < 32; k++) {
                float w = p * Vk[k];
                den += w;
                num += w * tab[im][k];
                p *= U;
            }
            lut[i] = __fdividef(num, den) * (1.0f / 31.0f);
        }
        __syncthreads();
    }

    // ======================= P3: apply (LUT lerp) =======================
    {
        const int im    = bid & 1;
        const int blkin = bid >> 1;          // 0..147
        const float* lut = dyn_smem;
        const float4* in4  = (const float4*)(dst + (size_t)im * N_VOX);
        float4*       out4 = (float4*)(out + (size_t)im * N_VOX);
        const int nthreads = 148 * NTHREADS;

        for (int i = blkin * NTHREADS + tid; i < N_VOX / 4; i += nthreads) {
            float4 v = in4[i];
            float vals[4] = {v.x, v.y, v.z, v.w};
            float res[4];
            #pragma unroll
            for (int e = 0; e < 4; e++) {
                float u = vals[e] * (float)LUT_N;
                int idx = (int)u;
                idx = min(max(idx, 0), LUT_N - 1);
                float f = u - (float)idx;
                float a = lut[idx];
                float b = lut[idx + 1];
                res[e] = a + f * (b - a);
            }
            out4[i] = make_float4(res[0], res[1], res[2], res[3]);
        }
    }
}

extern "C" void kernel_launch(void* const* d_in, const int* in_sizes, int n_in,
                              void* d_out, int out_size)
{
    const float* dst = (const float*)d_in[0];
    const float* ref = (const float*)d_in[1];
    float* out = (float*)d_out;

    const int dyn_bytes = 16 * SLOTS * 32 * sizeof(float);   // 73728 B
    cudaFuncSetAttribute(fused_kernel, cudaFuncAttributeMaxDynamicSharedMemorySize,
                         dyn_bytes);
    fused_kernel<<<NBLK, NTHREADS, dyn_bytes>>>(dst, ref, out);
}

// round 6
// speedup vs baseline: 1.8323x; 1.0756x over previous
#include <cuda_runtime.h>

// Histogram matching: BINS=32, SIGMA=5, DELTA=1
// Shapes: dst, ref: (2,1,64,128,128) fp32; out same.
#define N_VOX    (64 * 128 * 128)    // 1048576 voxels per image
#define N_IMG    2
#define NBLK     296                 // 2 blocks per SM (148 SMs), co-resident
#define NTHREADS 512                 // 16 warps
#define H_SUB    74                  // hist sub-blocks per job (4 jobs * 74 = 296)
#define SLOTS    35                  // per-warp hist slots: s = c + 1, c in [-1, 33] (+pad)
#define LUT_N    1024                // lerp intervals; nodes = LUT_N + 1

// Scratch (device globals; fully rewritten or self-restoring every launch)
__device__ float g_part[4 * H_SUB * 32];   // per-block histogram partials
__device__ int           g_bar_cnt  = 0;   // returns to 0 every launch
__device__ volatile int  g_bar_sense = 0;  // flips once per launch (value-agnostic)

// ---------------------------------------------------------------------------
// Single persistent kernel:
//  P1: soft histograms (4 jobs = {dst,ref} x {img0,img1}) -> g_part
//  [grid barrier]
//  P2: every block redundantly reduces g_part -> cdf, argmin table, and builds
//      a 1025-node (base,delta) matched-value LUT for its image in smem
//  P3: stream dst through the LUT (lerp) -> out
//
// P1 math: hist[c] = S(c) - S(c+1), S(c) = sigmoid(5*(x - c + 0.5)).
// 4-slot window c = j-1..j+2 (j = floor(x)), boundaries at c = j..j+2:
//   z_k = 5t + {2.5, -2.5, -7.5},  t = x - j in [0,1)
//   phi_{j+2} = S2 (upper tail folded in), phi_{j-1} = 1 - S0 (lower tail in)
//   S2 ~= E2*(1 - E2*(1 - E2))   (err <= 4e-5, avg 2e-6)
// Tail misplacement avg 1.1e-4/voxel, one bin, opposite directions, and the
// systematic part is common to dst & ref -> argmin comparison nearly unmoved.
// Mass per voxel is exactly 1 -> normalization exact.
// ---------------------------------------------------------------------------
extern __shared__ float dyn_smem[];   // P1: 16*35*32 floats; P2/P3: LUT

__global__ void __launch_bounds__(NTHREADS, 2)
fused_kernel(const float* __restrict__ dst, const float* __restrict__ ref,
             float* __restrict__ out)
{
    __shared__ float part2[16 * 32];
    __shared__ float red[128 * 4];
    __shared__ float cdf[4][32];
    __shared__ float tab[2][32];
    __shared__ float Vk[32];

    const int tid  = threadIdx.x;
    const int lane = tid & 31;
    const int warp = tid >> 5;
    const int bid  = blockIdx.x;

    // ======================= P1: soft histogram =======================
    {
        const int job = bid & 3;            // 0,1 = dst; 2,3 = ref
        const int sub = bid >> 2;           // 0..73
        const float* src = (job < 2 ? dst : ref) + (size_t)(job & 1) * N_VOX;

        float* hs = dyn_smem;               // [warp][slot][lane]
        for (int i = tid; i < 16 * SLOTS * 32; i += NTHREADS) hs[i] = 0.0f;
        __syncthreads();

        float* hp = &hs[warp * SLOTS * 32 + lane];

        const float4* src4 = (const float4*)src;
        const int N4     = N_VOX / 4;
        const int stride = H_SUB * NTHREADS;
        int i = sub * NTHREADS + tid;
        if (i < N4) {
            float4 v = src4[i];
            for (;;) {
                int nx = i + stride;
                bool more = nx < N4;
                float4 vn;
                if (more) vn = src4[nx];    // prefetch next tile
                float vals[4] = {v.x, v.y, v.z, v.w};
                #pragma unroll
                for (int e = 0; e < 4; e++) {
                    float x  = vals[e] * 31.0f;       // [0, 31)
                    int   j  = (int)x;                // floor (x >= 0)
                    float xj = (float)j;
                    float e5 = __expf((x - xj) * 5.0f);       // e^{5t}
                    float E0 = e5 * 12.182494f;               // e^{5t+2.5}
                    float E1 = e5 * 8.2084998e-2f;            // e^{5t-2.5}
                    float E2 = e5 * 5.5308438e-4f;            // e^{5t-7.5}
                    float S0 = __fdividef(E0, 1.0f + E0);
                    float S1 = __fdividef(E1, 1.0f + E1);
                    float S2 = E2 * fmaf(-E2, 1.0f - E2, 1.0f);  // E2(1-E2(1-E2))
                    float* p = hp + j * 32;           // slot(c) = c + 1
                    p[0 * 32] += 1.0f - S0;           // c = j-1 (lower tail in)
                    p[1 * 32] += S0 - S1;             // c = j
                    p[2 * 32] += S1 - S2;             // c = j+1
                    p[3 * 32] += S2;                  // c = j+2 (upper tail in)
                }
                if (!more) break;
                v = vn; i = nx;
            }
        }
        __syncthreads();

        // Reduce 16 warps x 32 lanes per bin; skewed lane start: conflict-free.
        {
            int w = warp, bin = lane;                 // 512 = 16 warps x 32 bins
            float s = 0.0f;
            #pragma unroll
            for (int k = 0; k < 32; k++) {
                int l = (lane + k) & 31;
                s += hs[(w * SLOTS + bin + 1) * 32 + l];
            }
            part2[w * 32 + bin] = s;
        }
        __syncthreads();
        if (tid < 32) {
            float s = 0.0f;
            #pragma unroll
            for (int w = 0; w < 16; w++) s += part2[w * 32 + tid];
            g_part[(job * H_SUB + sub) * 32 + tid] = s;
        }
    }

    // ======================= grid barrier =======================
    __threadfence();          // publish g_part
    __syncthreads();
    if (tid == 0) {
        int s = g_bar_sense;  // stable: flips only after ALL arrive
        int p = atomicAdd(&g_bar_cnt, 1);
        if (p == NBLK - 1) {
            g_bar_cnt = 0;    // self-reset for next launch
            __threadfence();
            g_bar_sense = s ^ 1;
        } else {
            while (g_bar_sense == s) __nanosleep(64);
        }
    }
    __syncthreads();
    __threadfence();          // acquire g_part

    // ======== P2: redundant per-block reduce + cdf + table + LUT ========
    {
        int pair = tid >> 2;          // 0..127 (job,bin) pairs, 4 summers each
        int q    = tid & 3;
        {
            int job = pair >> 5, bin = pair & 31;
            float s = 0.0f;
            for (int b = q; b < H_SUB; b += 4)
                s += g_part[(job * H_SUB + b) * 32 + bin];
            red[pair * 4 + q] = s;
        }
        if (tid < 32) Vk[tid] = __expf((float)(tid * tid) * -0.02f);  // e^{-k^2/50}
        __syncthreads();
        if (tid < 128) {
            int job = tid >> 5, bin = tid & 31;
            cdf[job][bin] = (red[tid * 4 + 0] + red[tid * 4 + 1])
                          + (red[tid * 4 + 2] + red[tid * 4 + 3]);
        }
        __syncthreads();
        if (tid < 4) {                 // normalize + cumsum (serial, tiny)
            float tot = 0.0f;
            for (int b = 0; b < 32; b++) tot += fabsf(cdf[tid][b]);
            tot = fmaxf(tot, 1e-12f);
            float run = 0.0f;
            for (int b = 0; b < 32; b++) { run += cdf[tid][b] / tot; cdf[tid][b] = run; }
        }
        __syncthreads();
        if (tid < 64) {                // argmin tables (first-match ties)
            int bc = tid >> 5, i = tid & 31;
            float cd = cdf[bc][i];
            int best = 0;
            float bd = fabsf(cd - cdf[bc + 2][0]);
            for (int jj = 1; jj < 32; jj++) {
                float d = fabsf(cd - cdf[bc + 2][jj]);
                if (d < bd) { bd = d; best = jj; }
            }
            tab[bc][i] = (float)best;
        }
        __syncthreads();

        // Build node values f[i] (reuse dyn_smem high region), then (base,delta)
        // pairs at the base. f(x) = softmax_k(-(x-k)^2/50) . tab / 31 with
        // exp(-(x-k)^2/50) = C * U^k * Vk, U = e^{x/25} (C cancels).
        const int im = bid & 1;
        float* fval = dyn_smem + 4096;
        for (int i = tid; i < LUT_N + 1; i += NTHREADS) {
            float x = (float)i * (31.0f / (float)LUT_N);
            float U = __expf(x * 0.04f);
            float p = 1.0f, num = 0.0f, den = 0.0f;
            #pragma unroll
            for (int k = 0; k < 32; k++) {
                float w = p * Vk[k];
                den += w;
                num += w * tab[im][k];
                p *= U;
            }
            fval[i] = __fdividef(num, den) * (1.0f / 31.0f);
        }
        __syncthreads();
        float2* lut2 = (float2*)dyn_smem;
        for (int i = tid; i < LUT_N; i += NTHREADS) {
            float a = fval[i], b = fval[i + 1];
            lut2[i] = make_float2(a, b - a);
        }
        __syncthreads();
    }

    // ======================= P3: apply (LUT lerp) =======================
    {
        const int im    = bid & 1;
        const int blkin = bid >> 1;          // 0..147
        const float2* lut2 = (const float2*)dyn_smem;
        const float4* in4  = (const float4*)(dst + (size_t)im * N_VOX);
        float4*       out4 = (float4*)(out + (size_t)im * N_VOX);
        const int N4     = N_VOX / 4;
        const int stride = 148 * NTHREADS;

        int i = blkin * NTHREADS + tid;
        if (i < N4) {
            float4 v = in4[i];
            for (;;) {
                int nx = i + stride;
                bool more = nx < N4;
                float4 vn;
                if (more) vn = in4[nx];
                float vals[4] = {v.x, v.y, v.z, v.w};
                float res[4];
                #pragma unroll
                for (int e = 0; e < 4; e++) {
                    float u = vals[e] * (float)LUT_N;
                    int idx = (int)u;
                    idx = min(max(idx, 0), LUT_N - 1);
                    float f = u - (float)idx;
                    float2 ld = lut2[idx];
                    res[e] = fmaf(f, ld.y, ld.x);
                }
                out4[i] = make_float4(res[0], res[1], res[2], res[3]);
                if (!more) break;
                v = vn; i = nx;
            }
        }
    }
}

extern "C" void kernel_launch(void* const* d_in, const int* in_sizes, int n_in,
                              void* d_out, int out_size)
{
    const float* dst = (const float*)d_in[0];
    const float* ref = (const float*)d_in[1];
    float* out = (float*)d_out;

    const int dyn_bytes = 16 * SLOTS * 32 * sizeof(float);   // 71680 B
    cudaFuncSetAttribute(fused_kernel, cudaFuncAttributeMaxDynamicSharedMemorySize,
                         dyn_bytes);
    fused_kernel<<<NBLK, NTHREADS, dyn_bytes>>>(dst, ref, out);
}